// round 1
// baseline (speedup 1.0000x reference)
#include <cuda_runtime.h>
#include <cuda_bf16.h>
#include <cstdint>

// Shapes (fixed for this problem)
#define NB 8
#define NL 4096
#define ND 1024
#define NM1 (NB*NL)      // 32768 tokens
#define NM4 (NM1/4)      // 8192
#define NM16 (NM1/16)    // 2048

// ---------------- static device scratch (no cudaMalloc allowed) ----------------
__device__ __nv_bfloat16 g_xb[(size_t)NM1*ND];     // clipped x in bf16 (64 MiB)
__device__ float         g_m4[(size_t)NM4*ND];     // group-4 means, fp32 (32 MiB)
__device__ float         g_m16[(size_t)NM16*ND];   // group-16 means, fp32 (8 MiB)
__device__ __nv_bfloat16 g_W1b[(size_t)ND*ND];     // W1 in bf16 (2 MiB)
__device__ float         g_logits[NM1*2];          // router logits accumulators
__device__ float         g_mix[16];                // [0..7]=a4 per batch, [8..15]=a16

__device__ __forceinline__ float clipf(float v, float lo, float hi) {
    return fminf(fmaxf(v, lo), hi);
}
__device__ __forceinline__ uint32_t smem_u32(const void* p) {
    return (uint32_t)__cvta_generic_to_shared(p);
}
__device__ __forceinline__ float to_tf32(float x) {
    uint32_t u;
    asm("cvt.rna.tf32.f32 %0, %1;" : "=r"(u) : "f"(x));
    return __uint_as_float(u);
}

// ---------------- zero logits ----------------
__global__ void zero_logits_kernel() {
    int i = blockIdx.x * blockDim.x + threadIdx.x;   // 64*256 = 16384 threads, 4 floats each
    float4 z = {0.f, 0.f, 0.f, 0.f};
    *(float4*)(g_logits + (size_t)i * 4) = z;
}

// ---------------- prep: clip + bf16 copy + m4/m16 means ----------------
// one block per 16 tokens; 256 threads, each owns 4 contiguous dims
__global__ void prep_kernel(const float* __restrict__ vt) {
    int g = blockIdx.x;          // 0..2047
    int t = threadIdx.x;         // 0..255
    int d = t * 4;
    size_t base = (size_t)g * 16 * ND;
    float sx4 = 0.f, sy4 = 0.f, sz4 = 0.f, sw4 = 0.f;
    float sx16 = 0.f, sy16 = 0.f, sz16 = 0.f, sw16 = 0.f;
    #pragma unroll
    for (int r = 0; r < 16; r++) {
        float4 v = *(const float4*)(vt + base + (size_t)r * ND + d);
        v.x = clipf(v.x, -4.f, 4.f);
        v.y = clipf(v.y, -4.f, 4.f);
        v.z = clipf(v.z, -4.f, 4.f);
        v.w = clipf(v.w, -4.f, 4.f);
        __nv_bfloat162* bp = (__nv_bfloat162*)(g_xb + base + (size_t)r * ND + d);
        bp[0] = __floats2bfloat162_rn(v.x, v.y);
        bp[1] = __floats2bfloat162_rn(v.z, v.w);
        sx4 += v.x; sy4 += v.y; sz4 += v.z; sw4 += v.w;
        if ((r & 3) == 3) {
            int r4 = g * 4 + (r >> 2);
            float4 o = {sx4 * 0.25f, sy4 * 0.25f, sz4 * 0.25f, sw4 * 0.25f};
            *(float4*)(g_m4 + (size_t)r4 * ND + d) = o;
            sx16 += sx4; sy16 += sy4; sz16 += sz4; sw16 += sw4;
            sx4 = sy4 = sz4 = sw4 = 0.f;
        }
    }
    const float inv16 = 1.f / 16.f;
    float4 o = {sx16 * inv16, sy16 * inv16, sz16 * inv16, sw16 * inv16};
    *(float4*)(g_m16 + (size_t)g * ND + d) = o;
}

// ---------------- W1 -> bf16 ----------------
__global__ void wconv_kernel(const float* __restrict__ W1) {
    int i = blockIdx.x * blockDim.x + threadIdx.x;   // 1024*256 threads, 4 elems each
    float4 v = *(const float4*)(W1 + (size_t)i * 4);
    __nv_bfloat162* bp = (__nv_bfloat162*)(g_W1b + (size_t)i * 4);
    bp[0] = __floats2bfloat162_rn(v.x, v.y);
    bp[1] = __floats2bfloat162_rn(v.z, v.w);
}

// ---------------- GEMM1 (bf16 mma): logits += relu(x@W1^T + b1) @ W2^T ----------------
// BM=128, BN=128, BK=32. 8 warps as 4(m)x2(n); warp tile 32x64. h never materialized.
__global__ void __launch_bounds__(256, 2) gemm1_kernel(
    const float* __restrict__ W2, const float* __restrict__ b1)
{
    __shared__ __align__(16) __nv_bfloat16 sA[128 * 32];
    __shared__ __align__(16) __nv_bfloat16 sB[128 * 32];
    int tid = threadIdx.x;
    int warp = tid >> 5, lane = tid & 31;
    int wm = warp >> 1, wn = warp & 1;
    int bm = blockIdx.y, bn = blockIdx.x;

    float acc[2][8][4];
    #pragma unroll
    for (int mi = 0; mi < 2; mi++)
        #pragma unroll
        for (int j = 0; j < 8; j++)
            #pragma unroll
            for (int k = 0; k < 4; k++) acc[mi][j][k] = 0.f;

    const __nv_bfloat16* gA = g_xb + (size_t)bm * 128 * ND;
    const __nv_bfloat16* gB = g_W1b + (size_t)bn * 128 * ND;

    for (int kb = 0; kb < 32; kb++) {
        #pragma unroll
        for (int p = 0; p < 2; p++) {
            int q = tid + p * 256;       // 0..511 chunk ids
            int row = q >> 2, c = q & 3; // 4x16B chunks per 64B row
            int cs = c ^ ((row >> 1) & 3);
            uint4 va = *(const uint4*)(gA + (size_t)row * ND + kb * 32 + c * 8);
            *(uint4*)(sA + row * 32 + cs * 8) = va;
            uint4 vb = *(const uint4*)(gB + (size_t)row * ND + kb * 32 + c * 8);
            *(uint4*)(sB + row * 32 + cs * 8) = vb;
        }
        __syncthreads();
        #pragma unroll
        for (int ks = 0; ks < 2; ks++) {
            uint32_t afr[2][4], bfr[8][2];
            #pragma unroll
            for (int mi = 0; mi < 2; mi++) {
                int row = wm * 32 + mi * 16 + (lane & 7) + ((lane >> 3) & 1) * 8;
                int kc = ks * 2 + (lane >> 4);
                int cs = kc ^ ((row >> 1) & 3);
                uint32_t addr = smem_u32(sA + row * 32 + cs * 8);
                asm volatile("ldmatrix.sync.aligned.m8n8.x4.shared.b16 {%0,%1,%2,%3},[%4];"
                    : "=r"(afr[mi][0]), "=r"(afr[mi][1]), "=r"(afr[mi][2]), "=r"(afr[mi][3])
                    : "r"(addr));
            }
            #pragma unroll
            for (int j = 0; j < 8; j += 2) {
                int row = wn * 64 + (j + (lane >> 4)) * 8 + (lane & 7);
                int kc = ks * 2 + ((lane >> 3) & 1);
                int cs = kc ^ ((row >> 1) & 3);
                uint32_t addr = smem_u32(sB + row * 32 + cs * 8);
                asm volatile("ldmatrix.sync.aligned.m8n8.x4.shared.b16 {%0,%1,%2,%3},[%4];"
                    : "=r"(bfr[j][0]), "=r"(bfr[j][1]), "=r"(bfr[j + 1][0]), "=r"(bfr[j + 1][1])
                    : "r"(addr));
            }
            #pragma unroll
            for (int mi = 0; mi < 2; mi++)
                #pragma unroll
                for (int j = 0; j < 8; j++) {
                    asm volatile(
                        "mma.sync.aligned.m16n8k16.row.col.f32.bf16.bf16.f32 "
                        "{%0,%1,%2,%3},{%4,%5,%6,%7},{%8,%9},{%0,%1,%2,%3};"
                        : "+f"(acc[mi][j][0]), "+f"(acc[mi][j][1]),
                          "+f"(acc[mi][j][2]), "+f"(acc[mi][j][3])
                        : "r"(afr[mi][0]), "r"(afr[mi][1]), "r"(afr[mi][2]), "r"(afr[mi][3]),
                          "r"(bfr[j][0]), "r"(bfr[j][1]));
                }
        }
        __syncthreads();
    }

    // epilogue: relu + partial dot with W2, atomic accumulate per-row logits
    int cb = bn * 128 + wn * 64;
    float w2a[8][2], w2b[8][2], b1p[8][2];
    #pragma unroll
    for (int j = 0; j < 8; j++)
        #pragma unroll
        for (int u = 0; u < 2; u++) {
            int col = cb + j * 8 + (lane & 3) * 2 + u;
            w2a[j][u] = __ldg(W2 + col);
            w2b[j][u] = __ldg(W2 + ND + col);
            b1p[j][u] = __ldg(b1 + col);
        }
    float s[2][2][2];
    #pragma unroll
    for (int mi = 0; mi < 2; mi++)
        #pragma unroll
        for (int hh = 0; hh < 2; hh++) { s[mi][hh][0] = 0.f; s[mi][hh][1] = 0.f; }
    #pragma unroll
    for (int mi = 0; mi < 2; mi++)
        #pragma unroll
        for (int j = 0; j < 8; j++) {
            float h0 = fmaxf(acc[mi][j][0] + b1p[j][0], 0.f);
            float h1 = fmaxf(acc[mi][j][1] + b1p[j][1], 0.f);
            float h2 = fmaxf(acc[mi][j][2] + b1p[j][0], 0.f);
            float h3 = fmaxf(acc[mi][j][3] + b1p[j][1], 0.f);
            s[mi][0][0] += h0 * w2a[j][0] + h1 * w2a[j][1];
            s[mi][0][1] += h0 * w2b[j][0] + h1 * w2b[j][1];
            s[mi][1][0] += h2 * w2a[j][0] + h3 * w2a[j][1];
            s[mi][1][1] += h2 * w2b[j][0] + h3 * w2b[j][1];
        }
    #pragma unroll
    for (int off = 1; off < 4; off <<= 1)
        #pragma unroll
        for (int mi = 0; mi < 2; mi++)
            #pragma unroll
            for (int hh = 0; hh < 2; hh++) {
                s[mi][hh][0] += __shfl_xor_sync(0xffffffffu, s[mi][hh][0], off);
                s[mi][hh][1] += __shfl_xor_sync(0xffffffffu, s[mi][hh][1], off);
            }
    if ((lane & 3) == 0) {
        #pragma unroll
        for (int mi = 0; mi < 2; mi++)
            #pragma unroll
            for (int hh = 0; hh < 2; hh++) {
                int rg = bm * 128 + wm * 32 + mi * 16 + hh * 8 + (lane >> 2);
                atomicAdd(&g_logits[2 * rg],     s[mi][hh][0]);
                atomicAdd(&g_logits[2 * rg + 1], s[mi][hh][1]);
            }
    }
}

// ---------------- router reduce: gumbel-softmax, per-batch mean, mix weights ----------------
__global__ void router_kernel(const float* __restrict__ gumbel, const float* __restrict__ b2) {
    int b = blockIdx.x, t = threadIdx.x;
    float b20 = __ldg(b2), b21 = __ldg(b2 + 1);
    float s0 = 0.f, s1 = 0.f;
    for (int tk = t; tk < NL; tk += 256) {
        int idx = b * NL + tk;
        float l0 = clipf(g_logits[2 * idx]     + b20, -15.f, 15.f);
        float l1 = clipf(g_logits[2 * idx + 1] + b21, -15.f, 15.f);
        float u0 = (l0 + gumbel[2 * idx])     * 2.0f;   // /TEMP, TEMP=0.5
        float u1 = (l1 + gumbel[2 * idx + 1]) * 2.0f;
        float p0 = 1.f / (1.f + expf(u1 - u0));
        float p1 = 1.f / (1.f + expf(u0 - u1));
        s0 += clipf(p0, 1e-7f, 1.f - 1e-7f);
        s1 += clipf(p1, 1e-7f, 1.f - 1e-7f);
    }
    __shared__ float r0[256], r1[256];
    r0[t] = s0; r1[t] = s1;
    __syncthreads();
    for (int o = 128; o > 0; o >>= 1) {
        if (t < o) { r0[t] += r0[t + o]; r1[t] += r1[t + o]; }
        __syncthreads();
    }
    if (t == 0) {
        float w4 = r0[0] / (float)NL, w16 = r1[0] / (float)NL;
        float ws = w4 + w16 + 1e-7f;
        g_mix[b]     = w4 / ws;
        g_mix[8 + b] = w16 / ws;
    }
}

// ---------------- tf32 GEMM for c4 (MODE 0: write) / c16 (MODE 1: RMW) ----------------
// BM=128, BN=128, BK=32; smem stride 36 floats (conflict-free for the frag loads)
template <int MODE>
__global__ void __launch_bounds__(256, 2) gemm_tf32_kernel(
    const float* __restrict__ W, const float* __restrict__ bias, float* __restrict__ out)
{
    __shared__ float sA[128 * 36];
    __shared__ float sB[128 * 36];
    int tid = threadIdx.x;
    int warp = tid >> 5, lane = tid & 31;
    int wm = warp >> 1, wn = warp & 1;
    int bm = blockIdx.y, bn = blockIdx.x;

    float acc[2][8][4];
    #pragma unroll
    for (int mi = 0; mi < 2; mi++)
        #pragma unroll
        for (int j = 0; j < 8; j++)
            #pragma unroll
            for (int k = 0; k < 4; k++) acc[mi][j][k] = 0.f;

    const float* gA = (MODE == 0 ? g_m4 : g_m16) + (size_t)bm * 128 * ND;
    const float* gB = W + (size_t)bn * 128 * ND;

    for (int kb = 0; kb < 32; kb++) {
        #pragma unroll
        for (int p = 0; p < 4; p++) {
            int q = tid + p * 256;       // 0..1023 float4 ids
            int row = q >> 3, c = q & 7; // 8 float4 per 32-float row
            float4 va = *(const float4*)(gA + (size_t)row * ND + kb * 32 + c * 4);
            float* da = sA + row * 36 + c * 4;
            da[0] = to_tf32(va.x); da[1] = to_tf32(va.y);
            da[2] = to_tf32(va.z); da[3] = to_tf32(va.w);
            float4 vb = *(const float4*)(gB + (size_t)row * ND + kb * 32 + c * 4);
            float* db = sB + row * 36 + c * 4;
            db[0] = to_tf32(vb.x); db[1] = to_tf32(vb.y);
            db[2] = to_tf32(vb.z); db[3] = to_tf32(vb.w);
        }
        __syncthreads();
        #pragma unroll
        for (int ks = 0; ks < 4; ks++) {
            uint32_t afr[2][4], bfr[8][2];
            #pragma unroll
            for (int mi = 0; mi < 2; mi++) {
                int r = wm * 32 + mi * 16 + (lane >> 2);
                int c = ks * 8 + (lane & 3);
                afr[mi][0] = __float_as_uint(sA[r * 36 + c]);
                afr[mi][1] = __float_as_uint(sA[(r + 8) * 36 + c]);
                afr[mi][2] = __float_as_uint(sA[r * 36 + c + 4]);
                afr[mi][3] = __float_as_uint(sA[(r + 8) * 36 + c + 4]);
            }
            #pragma unroll
            for (int j = 0; j < 8; j++) {
                int n = wn * 64 + j * 8 + (lane >> 2);
                int c = ks * 8 + (lane & 3);
                bfr[j][0] = __float_as_uint(sB[n * 36 + c]);
                bfr[j][1] = __float_as_uint(sB[n * 36 + c + 4]);
            }
            #pragma unroll
            for (int mi = 0; mi < 2; mi++)
                #pragma unroll
                for (int j = 0; j < 8; j++) {
                    asm volatile(
                        "mma.sync.aligned.m16n8k8.row.col.f32.tf32.tf32.f32 "
                        "{%0,%1,%2,%3},{%4,%5,%6,%7},{%8,%9},{%0,%1,%2,%3};"
                        : "+f"(acc[mi][j][0]), "+f"(acc[mi][j][1]),
                          "+f"(acc[mi][j][2]), "+f"(acc[mi][j][3])
                        : "r"(afr[mi][0]), "r"(afr[mi][1]), "r"(afr[mi][2]), "r"(afr[mi][3]),
                          "r"(bfr[j][0]), "r"(bfr[j][1]));
                }
        }
        __syncthreads();
    }

    // epilogue: clip(+-6), scale by per-batch mix weight, write/accumulate into out
    int cb = bn * 128 + wn * 64;
    float bp[8][2];
    #pragma unroll
    for (int j = 0; j < 8; j++)
        #pragma unroll
        for (int u = 0; u < 2; u++)
            bp[j][u] = __ldg(bias + cb + j * 8 + (lane & 3) * 2 + u);

    #pragma unroll
    for (int mi = 0; mi < 2; mi++) {
        #pragma unroll
        for (int hh = 0; hh < 2; hh++) {
            int r = bm * 128 + wm * 32 + mi * 16 + hh * 8 + (lane >> 2);
            float amix;
            size_t orow;
            if (MODE == 0) {               // c4: rows 0..8191 map 1:1 to out rows
                amix = g_mix[r >> 10];
                orow = (size_t)r;
            } else {                       // c16: row -> (b, l<256) of out
                int bb = r >> 8;
                amix = g_mix[8 + bb];
                orow = (size_t)bb * 1024 + (r & 255);
            }
            #pragma unroll
            for (int j = 0; j < 8; j++) {
                int c = cb + j * 8 + (lane & 3) * 2;
                float v0 = clipf(acc[mi][j][hh * 2 + 0] + bp[j][0], -6.f, 6.f);
                float v1 = clipf(acc[mi][j][hh * 2 + 1] + bp[j][1], -6.f, 6.f);
                float* o = out + orow * ND + c;
                if (MODE == 0) {
                    o[0] = amix * v0;
                    o[1] = amix * v1;
                } else {
                    o[0] = clipf(o[0] + amix * v0, -6.f, 6.f);
                    o[1] = clipf(o[1] + amix * v1, -6.f, 6.f);
                }
            }
        }
    }
}

// ---------------- launch ----------------
extern "C" void kernel_launch(void* const* d_in, const int* in_sizes, int n_in,
                              void* d_out, int out_size) {
    const float* vt     = (const float*)d_in[0];
    const float* gumbel = (const float*)d_in[1];
    const float* W1     = (const float*)d_in[2];
    const float* b1     = (const float*)d_in[3];
    const float* W2     = (const float*)d_in[4];
    const float* b2     = (const float*)d_in[5];
    const float* W4     = (const float*)d_in[6];
    const float* b4     = (const float*)d_in[7];
    const float* W16    = (const float*)d_in[8];
    const float* b16    = (const float*)d_in[9];
    float* out = (float*)d_out;

    zero_logits_kernel<<<64, 256>>>();
    prep_kernel<<<2048, 256>>>(vt);
    wconv_kernel<<<1024, 256>>>(W1);
    gemm1_kernel<<<dim3(8, 256), 256>>>(W2, b1);
    router_kernel<<<8, 256>>>(gumbel, b2);
    gemm_tf32_kernel<0><<<dim3(8, 64), 256>>>(W4, b4, out);
    gemm_tf32_kernel<1><<<dim3(8, 16), 256>>>(W16, b16, out);
}

// round 3
// speedup vs baseline: 1.4337x; 1.4337x over previous
#include <cuda_runtime.h>
#include <cuda_fp16.h>
#include <cstdint>

#define NB 8
#define NL 4096
#define ND 1024
#define NM1 (NB*NL)      // 32768
#define NM4 (NM1/4)      // 8192
#define NM16 (NM1/16)    // 2048

// ---------------- static device scratch ----------------
__device__ __half g_xh[(size_t)NM1*ND];     // clipped x, fp16 (64 MiB)
__device__ __half g_m4h[(size_t)NM4*ND];    // group-4 means, fp16
__device__ __half g_m16h[(size_t)NM16*ND];  // group-16 means, fp16
__device__ __half g_W1h[(size_t)ND*ND];
__device__ __half g_W4h[(size_t)ND*ND];
__device__ __half g_W16h[(size_t)ND*ND];
__device__ float  g_logits[NM1*2];
__device__ float  g_mix[16];                // [0..7]=a4, [8..15]=a16

__device__ __forceinline__ float clipf(float v, float lo, float hi) {
    return fminf(fmaxf(v, lo), hi);
}
__device__ __forceinline__ uint32_t smem_u32(const void* p) {
    return (uint32_t)__cvta_generic_to_shared(p);
}

// ---------------- zero logits ----------------
__global__ void zero_logits_kernel() {
    int i = blockIdx.x * blockDim.x + threadIdx.x;
    float4 z = {0.f, 0.f, 0.f, 0.f};
    *(float4*)(g_logits + (size_t)i * 4) = z;
}

// ---------------- prep: clip + fp16 copy + m4/m16 means ----------------
__global__ void prep_kernel(const float* __restrict__ vt) {
    int g = blockIdx.x;          // 0..2047 (16 tokens each)
    int t = threadIdx.x;         // 0..255
    int d = t * 4;
    size_t base = (size_t)g * 16 * ND;
    float sx4 = 0.f, sy4 = 0.f, sz4 = 0.f, sw4 = 0.f;
    float sx16 = 0.f, sy16 = 0.f, sz16 = 0.f, sw16 = 0.f;
    #pragma unroll
    for (int r = 0; r < 16; r++) {
        float4 v = *(const float4*)(vt + base + (size_t)r * ND + d);
        v.x = clipf(v.x, -4.f, 4.f);
        v.y = clipf(v.y, -4.f, 4.f);
        v.z = clipf(v.z, -4.f, 4.f);
        v.w = clipf(v.w, -4.f, 4.f);
        __half2* hp = (__half2*)(g_xh + base + (size_t)r * ND + d);
        hp[0] = __floats2half2_rn(v.x, v.y);
        hp[1] = __floats2half2_rn(v.z, v.w);
        sx4 += v.x; sy4 += v.y; sz4 += v.z; sw4 += v.w;
        if ((r & 3) == 3) {
            int r4 = g * 4 + (r >> 2);
            __half2* mp = (__half2*)(g_m4h + (size_t)r4 * ND + d);
            mp[0] = __floats2half2_rn(sx4 * 0.25f, sy4 * 0.25f);
            mp[1] = __floats2half2_rn(sz4 * 0.25f, sw4 * 0.25f);
            sx16 += sx4; sy16 += sy4; sz16 += sz4; sw16 += sw4;
            sx4 = sy4 = sz4 = sw4 = 0.f;
        }
    }
    const float i16 = 1.f / 16.f;
    __half2* mp = (__half2*)(g_m16h + (size_t)g * ND + d);
    mp[0] = __floats2half2_rn(sx16 * i16, sy16 * i16);
    mp[1] = __floats2half2_rn(sz16 * i16, sw16 * i16);
}

// ---------------- weight conversion to fp16 ----------------
__global__ void wprep_kernel(const float* __restrict__ W1, const float* __restrict__ W4,
                             const float* __restrict__ W16) {
    int id = blockIdx.x * blockDim.x + threadIdx.x;  // 786432 threads, one float4 each
    int s = id >> 18;
    int j = (id & 262143) << 2;
    const float* src = (s == 0) ? W1 : (s == 1) ? W4 : W16;
    __half* dst = (s == 0) ? g_W1h : (s == 1) ? g_W4h : g_W16h;
    float4 v = *(const float4*)(src + j);
    __half2* hp = (__half2*)(dst + j);
    hp[0] = __floats2half2_rn(v.x, v.y);
    hp[1] = __floats2half2_rn(v.z, v.w);
}

// ---------------- fp16 mma GEMM, CTA 128(or 64) x 256, BK=32, 4-stage cp.async ----------------
// MODE 0: gemm1 (A=g_xh)   -> fused relu + W2 dot -> atomic logits
// MODE 1: c4   (A=g_m4h)   -> clip*amix -> write out
// MODE 2: c16  (A=g_m16h)  -> clip*amix -> RMW out
// 8 warps as 2(m) x 4(n); warp tile (MI*16) x 64.
template<int MODE, int MI>
__global__ void __launch_bounds__(256, 1) gemm_h(
    const float* __restrict__ pb,
    const float* __restrict__ pw2,
    float* __restrict__ outp)
{
    constexpr int BM   = MI * 32;            // CTA M
    constexpr int ACH  = BM * 4;             // A 16B-chunks per stage
    constexpr int TCH  = ACH + 1024;         // total chunks per stage
    constexpr int STG  = (BM + 256) * 64;    // stage bytes
    constexpr int NK   = 32;                 // 1024 / 32

    extern __shared__ __align__(128) char smem[];
    uint32_t sb = smem_u32(smem);
    float* s_b   = (float*)(smem + 4 * STG);
    float* s_w2a = (float*)(smem + 4 * STG + 1024);
    float* s_w2b = (float*)(smem + 4 * STG + 2048);

    int tid = threadIdx.x, warp = tid >> 5, lane = tid & 31;
    int wm = warp >> 2, wn = warp & 3;       // 2 x 4
    int mb = blockIdx.y, nb = blockIdx.x;

    // epilogue params
    if (tid < 256) {
        s_b[tid] = pb[nb * 256 + tid];
        if (MODE == 0) {
            s_w2a[tid] = pw2[nb * 256 + tid];
            s_w2b[tid] = pw2[ND + nb * 256 + tid];
        }
    }

    const char* Ab;
    const char* Bb;
    if (MODE == 0)      { Ab = (const char*)g_xh   + (size_t)mb * BM * 2048; Bb = (const char*)g_W1h  + (size_t)nb * 256 * 2048; }
    else if (MODE == 1) { Ab = (const char*)g_m4h  + (size_t)mb * BM * 2048; Bb = (const char*)g_W4h  + (size_t)nb * 256 * 2048; }
    else                { Ab = (const char*)g_m16h + (size_t)mb * BM * 2048; Bb = (const char*)g_W16h + (size_t)nb * 256 * 2048; }

    auto load_stage = [&](int st, int k) {
        uint32_t base = sb + st * STG;
        #pragma unroll
        for (int i = 0; i < TCH / 256; i++) {
            int id = tid + i * 256;
            bool isB = id >= ACH;
            int l2 = isB ? id - ACH : id;
            int row = l2 >> 2, c = l2 & 3;
            const char* src = (isB ? Bb : Ab) + (size_t)row * 2048 + (size_t)k * 64 + c * 16;
            uint32_t dst = base + (isB ? BM * 64 : 0) + row * 64 + ((c ^ ((row >> 1) & 3)) << 4);
            asm volatile("cp.async.cg.shared.global [%0], [%1], 16;" :: "r"(dst), "l"(src));
        }
        asm volatile("cp.async.commit_group;" ::: "memory");
    };

    float acc[MI][8][4];
    #pragma unroll
    for (int mi = 0; mi < MI; mi++)
        #pragma unroll
        for (int j = 0; j < 8; j++)
            #pragma unroll
            for (int q = 0; q < 4; q++) acc[mi][j][q] = 0.f;

    load_stage(0, 0);
    load_stage(1, 1);
    load_stage(2, 2);

    for (int k = 0; k < NK; k++) {
        asm volatile("cp.async.wait_group 2;" ::: "memory");
        __syncthreads();
        if (k + 3 < NK) load_stage((k + 3) & 3, k + 3);
        else            asm volatile("cp.async.commit_group;" ::: "memory");

        uint32_t pA = sb + (k & 3) * STG;
        uint32_t pB = pA + BM * 64;
        #pragma unroll
        for (int ks = 0; ks < 2; ks++) {
            uint32_t afr[MI][4], bfr[8][2];
            #pragma unroll
            for (int mi = 0; mi < MI; mi++) {
                int row = wm * (MI * 16) + mi * 16 + (lane & 7) + ((lane >> 3) & 1) * 8;
                int kc = ks * 2 + (lane >> 4);
                uint32_t addr = pA + row * 64 + ((kc ^ ((row >> 1) & 3)) << 4);
                asm volatile("ldmatrix.sync.aligned.m8n8.x4.shared.b16 {%0,%1,%2,%3},[%4];"
                    : "=r"(afr[mi][0]), "=r"(afr[mi][1]), "=r"(afr[mi][2]), "=r"(afr[mi][3])
                    : "r"(addr));
            }
            #pragma unroll
            for (int j = 0; j < 8; j += 2) {
                int row = wn * 64 + (j + (lane >> 4)) * 8 + (lane & 7);
                int kc = ks * 2 + ((lane >> 3) & 1);
                uint32_t addr = pB + row * 64 + ((kc ^ ((row >> 1) & 3)) << 4);
                asm volatile("ldmatrix.sync.aligned.m8n8.x4.shared.b16 {%0,%1,%2,%3},[%4];"
                    : "=r"(bfr[j][0]), "=r"(bfr[j][1]), "=r"(bfr[j + 1][0]), "=r"(bfr[j + 1][1])
                    : "r"(addr));
            }
            #pragma unroll
            for (int mi = 0; mi < MI; mi++)
                #pragma unroll
                for (int j = 0; j < 8; j++) {
                    asm volatile(
                        "mma.sync.aligned.m16n8k16.row.col.f32.f16.f16.f32 "
                        "{%0,%1,%2,%3},{%4,%5,%6,%7},{%8,%9},{%0,%1,%2,%3};"
                        : "+f"(acc[mi][j][0]), "+f"(acc[mi][j][1]),
                          "+f"(acc[mi][j][2]), "+f"(acc[mi][j][3])
                        : "r"(afr[mi][0]), "r"(afr[mi][1]), "r"(afr[mi][2]), "r"(afr[mi][3]),
                          "r"(bfr[j][0]), "r"(bfr[j][1]));
                }
        }
    }

    // ---------------- epilogue ----------------
    if (MODE == 0) {
        #pragma unroll
        for (int mi = 0; mi < MI; mi++) {
            float s[2][2] = {{0.f, 0.f}, {0.f, 0.f}};
            #pragma unroll
            for (int j = 0; j < 8; j++)
                #pragma unroll
                for (int q = 0; q < 4; q++) {
                    int col = wn * 64 + j * 8 + (lane & 3) * 2 + (q & 1);
                    float h = fmaxf(acc[mi][j][q] + s_b[col], 0.f);
                    s[q >> 1][0] += h * s_w2a[col];
                    s[q >> 1][1] += h * s_w2b[col];
                }
            #pragma unroll
            for (int off = 1; off < 4; off <<= 1)
                #pragma unroll
                for (int hh = 0; hh < 2; hh++) {
                    s[hh][0] += __shfl_xor_sync(0xffffffffu, s[hh][0], off);
                    s[hh][1] += __shfl_xor_sync(0xffffffffu, s[hh][1], off);
                }
            if ((lane & 3) == 0) {
                #pragma unroll
                for (int hh = 0; hh < 2; hh++) {
                    int row = mb * BM + wm * (MI * 16) + mi * 16 + hh * 8 + (lane >> 2);
                    atomicAdd(&g_logits[2 * row],     s[hh][0]);
                    atomicAdd(&g_logits[2 * row + 1], s[hh][1]);
                }
            }
        }
    } else {
        #pragma unroll
        for (int mi = 0; mi < MI; mi++) {
            #pragma unroll
            for (int hh = 0; hh < 2; hh++) {
                int r = mb * BM + wm * (MI * 16) + mi * 16 + hh * 8 + (lane >> 2);
                float amix;
                size_t orow;
                if (MODE == 1) { amix = g_mix[r >> 10]; orow = (size_t)r; }
                else { int bb = r >> 8; amix = g_mix[8 + bb]; orow = (size_t)bb * 1024 + (r & 255); }
                float* obase = outp + orow * ND + nb * 256 + wn * 64;
                #pragma unroll
                for (int j = 0; j < 8; j++) {
                    int cl = wn * 64 + j * 8 + (lane & 3) * 2;
                    float v0 = amix * clipf(acc[mi][j][hh * 2 + 0] + s_b[cl],     -6.f, 6.f);
                    float v1 = amix * clipf(acc[mi][j][hh * 2 + 1] + s_b[cl + 1], -6.f, 6.f);
                    float* op = obase + j * 8 + (lane & 3) * 2;
                    if (MODE == 1) {
                        float2 o = {v0, v1};
                        *(float2*)op = o;
                    } else {
                        float2 o = *(float2*)op;
                        o.x = clipf(o.x + v0, -6.f, 6.f);
                        o.y = clipf(o.y + v1, -6.f, 6.f);
                        *(float2*)op = o;
                    }
                }
            }
        }
    }
}

// ---------------- router reduce ----------------
__global__ void router_kernel(const float* __restrict__ gumbel, const float* __restrict__ b2) {
    int b = blockIdx.x, t = threadIdx.x;
    float b20 = __ldg(b2), b21 = __ldg(b2 + 1);
    float s0 = 0.f, s1 = 0.f;
    for (int tk = t; tk < NL; tk += 256) {
        int idx = b * NL + tk;
        float l0 = clipf(g_logits[2 * idx]     + b20, -15.f, 15.f);
        float l1 = clipf(g_logits[2 * idx + 1] + b21, -15.f, 15.f);
        float u0 = (l0 + gumbel[2 * idx])     * 2.0f;   // /TEMP, TEMP=0.5
        float u1 = (l1 + gumbel[2 * idx + 1]) * 2.0f;
        float p0 = 1.f / (1.f + expf(u1 - u0));
        float p1 = 1.f / (1.f + expf(u0 - u1));
        s0 += clipf(p0, 1e-7f, 1.f - 1e-7f);
        s1 += clipf(p1, 1e-7f, 1.f - 1e-7f);
    }
    __shared__ float r0[256], r1[256];
    r0[t] = s0; r1[t] = s1;
    __syncthreads();
    for (int o = 128; o > 0; o >>= 1) {
        if (t < o) { r0[t] += r0[t + o]; r1[t] += r1[t + o]; }
        __syncthreads();
    }
    if (t == 0) {
        float w4 = r0[0] / (float)NL, w16 = r1[0] / (float)NL;
        float ws = w4 + w16 + 1e-7f;
        g_mix[b]     = w4 / ws;
        g_mix[8 + b] = w16 / ws;
    }
}

// ---------------- launch ----------------
extern "C" void kernel_launch(void* const* d_in, const int* in_sizes, int n_in,
                              void* d_out, int out_size) {
    const float* vt     = (const float*)d_in[0];
    const float* gumbel = (const float*)d_in[1];
    const float* W1     = (const float*)d_in[2];
    const float* b1     = (const float*)d_in[3];
    const float* W2     = (const float*)d_in[4];
    const float* b2     = (const float*)d_in[5];
    const float* W4     = (const float*)d_in[6];
    const float* b4     = (const float*)d_in[7];
    const float* W16    = (const float*)d_in[8];
    const float* b16    = (const float*)d_in[9];
    float* out = (float*)d_out;

    // smem: 4 stages + 3KB epilogue params
    const int SM128 = 4 * (128 + 256) * 64 + 3072;   // 101376
    const int SM64  = 4 * (64 + 256) * 64 + 3072;    //  84992
    cudaFuncSetAttribute(gemm_h<0,4>, cudaFuncAttributeMaxDynamicSharedMemorySize, SM128);
    cudaFuncSetAttribute(gemm_h<1,4>, cudaFuncAttributeMaxDynamicSharedMemorySize, SM128);
    cudaFuncSetAttribute(gemm_h<2,2>, cudaFuncAttributeMaxDynamicSharedMemorySize, SM64);

    zero_logits_kernel<<<64, 256>>>();
    wprep_kernel<<<3072, 256>>>(W1, W4, W16);
    prep_kernel<<<2048, 256>>>(vt);
    gemm_h<0,4><<<dim3(4, 256), 256, SM128>>>(b1, W2, nullptr);
    router_kernel<<<8, 256>>>(gumbel, b2);
    gemm_h<1,4><<<dim3(4, 64), 256, SM128>>>(b4, nullptr, out);
    gemm_h<2,2><<<dim3(4, 32), 256, SM64>>>(b16, nullptr, out);
}

// round 5
// speedup vs baseline: 1.5798x; 1.1019x over previous
#include <cuda_runtime.h>
#include <cuda_fp16.h>
#include <cstdint>

#define NB 8
#define NL 4096
#define ND 1024
#define NM1 (NB*NL)      // 32768
#define NM4 (NM1/4)      // 8192
#define NM16 (NM1/16)    // 2048

// ---------------- static device scratch ----------------
__device__ __half g_xh[(size_t)NM1*ND];     // clipped x, fp16 (64 MiB)
__device__ __half g_m4h[(size_t)NM4*ND];    // group-4 means, fp16
__device__ __half g_m16h[(size_t)NM16*ND];  // group-16 means, fp16
__device__ __half g_W1h[(size_t)ND*ND];
__device__ __half g_W4h[(size_t)ND*ND];
__device__ __half g_W16h[(size_t)ND*ND];
__device__ float  g_logits[NM1*2];
__device__ float  g_mix[16];                // [0..7]=a4, [8..15]=a16

__device__ __forceinline__ float clipf(float v, float lo, float hi) {
    return fminf(fmaxf(v, lo), hi);
}
__device__ __forceinline__ uint32_t smem_u32(const void* p) {
    return (uint32_t)__cvta_generic_to_shared(p);
}

// ---------------- zero logits ----------------
__global__ void zero_logits_kernel() {
    int i = blockIdx.x * blockDim.x + threadIdx.x;
    float4 z = {0.f, 0.f, 0.f, 0.f};
    *(float4*)(g_logits + (size_t)i * 4) = z;
}

// ---------------- prep: clip + fp16 copy + m4/m16 means ----------------
__global__ void prep_kernel(const float* __restrict__ vt) {
    int g = blockIdx.x;          // 0..2047 (16 tokens each)
    int t = threadIdx.x;         // 0..255
    int d = t * 4;
    size_t base = (size_t)g * 16 * ND;
    float sx4 = 0.f, sy4 = 0.f, sz4 = 0.f, sw4 = 0.f;
    float sx16 = 0.f, sy16 = 0.f, sz16 = 0.f, sw16 = 0.f;
    #pragma unroll
    for (int r = 0; r < 16; r++) {
        float4 v = *(const float4*)(vt + base + (size_t)r * ND + d);
        v.x = clipf(v.x, -4.f, 4.f);
        v.y = clipf(v.y, -4.f, 4.f);
        v.z = clipf(v.z, -4.f, 4.f);
        v.w = clipf(v.w, -4.f, 4.f);
        __half2* hp = (__half2*)(g_xh + base + (size_t)r * ND + d);
        hp[0] = __floats2half2_rn(v.x, v.y);
        hp[1] = __floats2half2_rn(v.z, v.w);
        sx4 += v.x; sy4 += v.y; sz4 += v.z; sw4 += v.w;
        if ((r & 3) == 3) {
            int r4 = g * 4 + (r >> 2);
            __half2* mp = (__half2*)(g_m4h + (size_t)r4 * ND + d);
            mp[0] = __floats2half2_rn(sx4 * 0.25f, sy4 * 0.25f);
            mp[1] = __floats2half2_rn(sz4 * 0.25f, sw4 * 0.25f);
            sx16 += sx4; sy16 += sy4; sz16 += sz4; sw16 += sw4;
            sx4 = sy4 = sz4 = sw4 = 0.f;
        }
    }
    const float i16 = 1.f / 16.f;
    __half2* mp = (__half2*)(g_m16h + (size_t)g * ND + d);
    mp[0] = __floats2half2_rn(sx16 * i16, sy16 * i16);
    mp[1] = __floats2half2_rn(sz16 * i16, sw16 * i16);
}

// ---------------- weight conversion to fp16 ----------------
__global__ void wprep_kernel(const float* __restrict__ W1, const float* __restrict__ W4,
                             const float* __restrict__ W16) {
    int id = blockIdx.x * blockDim.x + threadIdx.x;  // 786432 threads, one float4 each
    int s = id >> 18;
    int j = (id & 262143) << 2;
    const float* src = (s == 0) ? W1 : (s == 1) ? W4 : W16;
    __half* dst = (s == 0) ? g_W1h : (s == 1) ? g_W4h : g_W16h;
    float4 v = *(const float4*)(src + j);
    __half2* hp = (__half2*)(dst + j);
    hp[0] = __floats2half2_rn(v.x, v.y);
    hp[1] = __floats2half2_rn(v.z, v.w);
}

// ---------------- fp16 mma GEMM, CTA (MI*32) x 256, BK=32, 3-stage cp.async ----------------
// MODE 0: gemm1 (A=g_xh), FP16 accumulators -> fused relu + W2 dot -> atomic logits
// MODE 1: c4   (A=g_m4h), FP32 acc -> clip*amix -> write out
// MODE 2: c16  (A=g_m16h), FP32 acc -> clip*amix -> RMW out
// 8 warps as 2(m) x 4(n); warp tile (MI*16) x 64.
template<int MODE, int MI>
__global__ void __launch_bounds__(256, (MODE == 0) ? 2 : 1) gemm_h(
    const float* __restrict__ pb,
    const float* __restrict__ pw2,
    float* __restrict__ outp)
{
    constexpr int BM   = MI * 32;            // CTA M
    constexpr int ACH  = BM * 4;             // A 16B-chunks per stage
    constexpr int TCH  = ACH + 1024;         // total chunks per stage
    constexpr int STG  = (BM + 256) * 64;    // stage bytes
    constexpr int NK   = 32;                 // 1024 / 32

    extern __shared__ __align__(128) char smem[];
    uint32_t sb = smem_u32(smem);
    float* s_b   = (float*)(smem + 3 * STG);
    float* s_w2a = (float*)(smem + 3 * STG + 1024);
    float* s_w2b = (float*)(smem + 3 * STG + 2048);

    int tid = threadIdx.x, warp = tid >> 5, lane = tid & 31;
    int wm = warp >> 2, wn = warp & 3;       // 2 x 4
    int mb = blockIdx.y, nb = blockIdx.x;

    // epilogue params
    if (tid < 256) {
        s_b[tid] = pb[nb * 256 + tid];
        if (MODE == 0) {
            s_w2a[tid] = pw2[nb * 256 + tid];
            s_w2b[tid] = pw2[ND + nb * 256 + tid];
        }
    }

    const char* Ab;
    const char* Bb;
    if (MODE == 0)      { Ab = (const char*)g_xh   + (size_t)mb * BM * 2048; Bb = (const char*)g_W1h  + (size_t)nb * 256 * 2048; }
    else if (MODE == 1) { Ab = (const char*)g_m4h  + (size_t)mb * BM * 2048; Bb = (const char*)g_W4h  + (size_t)nb * 256 * 2048; }
    else                { Ab = (const char*)g_m16h + (size_t)mb * BM * 2048; Bb = (const char*)g_W16h + (size_t)nb * 256 * 2048; }

    auto load_stage = [&](int st, int k) {
        uint32_t base = sb + st * STG;
        #pragma unroll
        for (int i = 0; i < TCH / 256; i++) {
            int id = tid + i * 256;
            bool isB = id >= ACH;
            int l2 = isB ? id - ACH : id;
            int row = l2 >> 2, c = l2 & 3;
            const char* src = (isB ? Bb : Ab) + (size_t)row * 2048 + (size_t)k * 64 + c * 16;
            uint32_t dst = base + (isB ? BM * 64 : 0) + row * 64 + ((c ^ ((row >> 1) & 3)) << 4);
            asm volatile("cp.async.cg.shared.global [%0], [%1], 16;" :: "r"(dst), "l"(src));
        }
        asm volatile("cp.async.commit_group;" ::: "memory");
    };

    // accumulators (only one set used per MODE)
    uint32_t acch[MI][8][2];
    float    accf[MI][8][4];
    if constexpr (MODE == 0) {
        #pragma unroll
        for (int mi = 0; mi < MI; mi++)
            #pragma unroll
            for (int j = 0; j < 8; j++) { acch[mi][j][0] = 0u; acch[mi][j][1] = 0u; }
    } else {
        #pragma unroll
        for (int mi = 0; mi < MI; mi++)
            #pragma unroll
            for (int j = 0; j < 8; j++)
                #pragma unroll
                for (int q = 0; q < 4; q++) accf[mi][j][q] = 0.f;
    }

    load_stage(0, 0);
    load_stage(1, 1);

    int st = 0;
    for (int k = 0; k < NK; k++) {
        asm volatile("cp.async.wait_group 1;" ::: "memory");
        __syncthreads();
        if (k + 2 < NK) {
            int st2 = st + 2; if (st2 >= 3) st2 -= 3;
            load_stage(st2, k + 2);
        } else {
            asm volatile("cp.async.commit_group;" ::: "memory");
        }

        uint32_t pA = sb + st * STG;
        uint32_t pB = pA + BM * 64;
        #pragma unroll
        for (int ks = 0; ks < 2; ks++) {
            uint32_t afr[MI][4], bfr[8][2];
            #pragma unroll
            for (int mi = 0; mi < MI; mi++) {
                int row = wm * (MI * 16) + mi * 16 + (lane & 7) + ((lane >> 3) & 1) * 8;
                int kc = ks * 2 + (lane >> 4);
                uint32_t addr = pA + row * 64 + ((kc ^ ((row >> 1) & 3)) << 4);
                asm volatile("ldmatrix.sync.aligned.m8n8.x4.shared.b16 {%0,%1,%2,%3},[%4];"
                    : "=r"(afr[mi][0]), "=r"(afr[mi][1]), "=r"(afr[mi][2]), "=r"(afr[mi][3])
                    : "r"(addr));
            }
            #pragma unroll
            for (int j = 0; j < 8; j += 2) {
                int row = wn * 64 + (j + (lane >> 4)) * 8 + (lane & 7);
                int kc = ks * 2 + ((lane >> 3) & 1);
                uint32_t addr = pB + row * 64 + ((kc ^ ((row >> 1) & 3)) << 4);
                asm volatile("ldmatrix.sync.aligned.m8n8.x4.shared.b16 {%0,%1,%2,%3},[%4];"
                    : "=r"(bfr[j][0]), "=r"(bfr[j][1]), "=r"(bfr[j + 1][0]), "=r"(bfr[j + 1][1])
                    : "r"(addr));
            }
            #pragma unroll
            for (int mi = 0; mi < MI; mi++)
                #pragma unroll
                for (int j = 0; j < 8; j++) {
                    if constexpr (MODE == 0) {
                        asm volatile(
                            "mma.sync.aligned.m16n8k16.row.col.f16.f16.f16.f16 "
                            "{%0,%1},{%2,%3,%4,%5},{%6,%7},{%0,%1};"
                            : "+r"(acch[mi][j][0]), "+r"(acch[mi][j][1])
                            : "r"(afr[mi][0]), "r"(afr[mi][1]), "r"(afr[mi][2]), "r"(afr[mi][3]),
                              "r"(bfr[j][0]), "r"(bfr[j][1]));
                    } else {
                        asm volatile(
                            "mma.sync.aligned.m16n8k16.row.col.f32.f16.f16.f32 "
                            "{%0,%1,%2,%3},{%4,%5,%6,%7},{%8,%9},{%0,%1,%2,%3};"
                            : "+f"(accf[mi][j][0]), "+f"(accf[mi][j][1]),
                              "+f"(accf[mi][j][2]), "+f"(accf[mi][j][3])
                            : "r"(afr[mi][0]), "r"(afr[mi][1]), "r"(afr[mi][2]), "r"(afr[mi][3]),
                              "r"(bfr[j][0]), "r"(bfr[j][1]));
                    }
                }
        }
        st++; if (st >= 3) st -= 3;
    }

    // ---------------- epilogue ----------------
    if constexpr (MODE == 0) {
        #pragma unroll
        for (int mi = 0; mi < MI; mi++) {
            float s[2][2] = {{0.f, 0.f}, {0.f, 0.f}};
            #pragma unroll
            for (int j = 0; j < 8; j++) {
                int colb = wn * 64 + j * 8 + (lane & 3) * 2;
                float2 v0 = __half22float2(*(__half2*)&acch[mi][j][0]);
                float2 v1 = __half22float2(*(__half2*)&acch[mi][j][1]);
                float h00 = fmaxf(v0.x + s_b[colb],     0.f);
                float h01 = fmaxf(v0.y + s_b[colb + 1], 0.f);
                float h10 = fmaxf(v1.x + s_b[colb],     0.f);
                float h11 = fmaxf(v1.y + s_b[colb + 1], 0.f);
                s[0][0] += h00 * s_w2a[colb] + h01 * s_w2a[colb + 1];
                s[0][1] += h00 * s_w2b[colb] + h01 * s_w2b[colb + 1];
                s[1][0] += h10 * s_w2a[colb] + h11 * s_w2a[colb + 1];
                s[1][1] += h10 * s_w2b[colb] + h11 * s_w2b[colb + 1];
            }
            #pragma unroll
            for (int off = 1; off < 4; off <<= 1)
                #pragma unroll
                for (int hh = 0; hh < 2; hh++) {
                    s[hh][0] += __shfl_xor_sync(0xffffffffu, s[hh][0], off);
                    s[hh][1] += __shfl_xor_sync(0xffffffffu, s[hh][1], off);
                }
            if ((lane & 3) == 0) {
                #pragma unroll
                for (int hh = 0; hh < 2; hh++) {
                    int row = mb * BM + wm * (MI * 16) + mi * 16 + hh * 8 + (lane >> 2);
                    atomicAdd(&g_logits[2 * row],     s[hh][0]);
                    atomicAdd(&g_logits[2 * row + 1], s[hh][1]);
                }
            }
        }
    } else {
        #pragma unroll
        for (int mi = 0; mi < MI; mi++) {
            #pragma unroll
            for (int hh = 0; hh < 2; hh++) {
                int r = mb * BM + wm * (MI * 16) + mi * 16 + hh * 8 + (lane >> 2);
                float amix;
                size_t orow;
                if (MODE == 1) { amix = g_mix[r >> 10]; orow = (size_t)r; }
                else { int bb = r >> 8; amix = g_mix[8 + bb]; orow = (size_t)bb * 1024 + (r & 255); }
                float* obase = outp + orow * ND + nb * 256 + wn * 64;
                #pragma unroll
                for (int j = 0; j < 8; j++) {
                    int cl = wn * 64 + j * 8 + (lane & 3) * 2;
                    float v0 = amix * clipf(accf[mi][j][hh * 2 + 0] + s_b[cl],     -6.f, 6.f);
                    float v1 = amix * clipf(accf[mi][j][hh * 2 + 1] + s_b[cl + 1], -6.f, 6.f);
                    float* op = obase + j * 8 + (lane & 3) * 2;
                    if (MODE == 1) {
                        float2 o = {v0, v1};
                        *(float2*)op = o;
                    } else {
                        float2 o = *(float2*)op;
                        o.x = clipf(o.x + v0, -6.f, 6.f);
                        o.y = clipf(o.y + v1, -6.f, 6.f);
                        *(float2*)op = o;
                    }
                }
            }
        }
    }
}

// ---------------- router reduce ----------------
__global__ void router_kernel(const float* __restrict__ gumbel, const float* __restrict__ b2) {
    int b = blockIdx.x, t = threadIdx.x;
    float b20 = __ldg(b2), b21 = __ldg(b2 + 1);
    float s0 = 0.f, s1 = 0.f;
    for (int tk = t; tk < NL; tk += 256) {
        int idx = b * NL + tk;
        float l0 = clipf(g_logits[2 * idx]     + b20, -15.f, 15.f);
        float l1 = clipf(g_logits[2 * idx + 1] + b21, -15.f, 15.f);
        float u0 = (l0 + gumbel[2 * idx])     * 2.0f;   // /TEMP, TEMP=0.5
        float u1 = (l1 + gumbel[2 * idx + 1]) * 2.0f;
        float p0 = 1.f / (1.f + expf(u1 - u0));
        float p1 = 1.f / (1.f + expf(u0 - u1));
        s0 += clipf(p0, 1e-7f, 1.f - 1e-7f);
        s1 += clipf(p1, 1e-7f, 1.f - 1e-7f);
    }
    __shared__ float r0[256], r1[256];
    r0[t] = s0; r1[t] = s1;
    __syncthreads();
    for (int o = 128; o > 0; o >>= 1) {
        if (t < o) { r0[t] += r0[t + o]; r1[t] += r1[t + o]; }
        __syncthreads();
    }
    if (t == 0) {
        float w4 = r0[0] / (float)NL, w16 = r1[0] / (float)NL;
        float ws = w4 + w16 + 1e-7f;
        g_mix[b]     = w4 / ws;
        g_mix[8 + b] = w16 / ws;
    }
}

// ---------------- launch ----------------
extern "C" void kernel_launch(void* const* d_in, const int* in_sizes, int n_in,
                              void* d_out, int out_size) {
    const float* vt     = (const float*)d_in[0];
    const float* gumbel = (const float*)d_in[1];
    const float* W1     = (const float*)d_in[2];
    const float* b1     = (const float*)d_in[3];
    const float* W2     = (const float*)d_in[4];
    const float* b2     = (const float*)d_in[5];
    const float* W4     = (const float*)d_in[6];
    const float* b4     = (const float*)d_in[7];
    const float* W16    = (const float*)d_in[8];
    const float* b16    = (const float*)d_in[9];
    float* out = (float*)d_out;

    // smem: 3 stages + 3KB epilogue params
    const int SM128 = 3 * (128 + 256) * 64 + 3072;   // 76800
    const int SM64  = 3 * (64 + 256) * 64 + 3072;    // 64512
    cudaFuncSetAttribute(gemm_h<0,4>, cudaFuncAttributeMaxDynamicSharedMemorySize, SM128);
    cudaFuncSetAttribute(gemm_h<1,4>, cudaFuncAttributeMaxDynamicSharedMemorySize, SM128);
    cudaFuncSetAttribute(gemm_h<2,2>, cudaFuncAttributeMaxDynamicSharedMemorySize, SM64);

    zero_logits_kernel<<<64, 256>>>();
    wprep_kernel<<<3072, 256>>>(W1, W4, W16);
    prep_kernel<<<2048, 256>>>(vt);
    gemm_h<0,4><<<dim3(4, 256), 256, SM128>>>(b1, W2, nullptr);
    router_kernel<<<8, 256>>>(gumbel, b2);
    gemm_h<1,4><<<dim3(4, 64), 256, SM128>>>(b4, nullptr, out);
    gemm_h<2,2><<<dim3(4, 32), 256, SM64>>>(b16, nullptr, out);
}